// round 1
// baseline (speedup 1.0000x reference)
#include <cuda_runtime.h>
#include <math.h>

// Problem constants
#define Bc 2
#define Tc 2048
#define Dc 1024
#define Hc 16
#define DHc 64
#define NBc 32
#define ROWS (Bc*Tc)          // 4096

// ---------------- scratch (static device memory; no allocations) ----------------
__device__ float g_h   [ (size_t)ROWS * Dc ];
__device__ float g_tmp [ (size_t)ROWS * Dc ];
__device__ float g_q   [ (size_t)ROWS * Dc ];
__device__ float g_k   [ (size_t)ROWS * Dc ];
__device__ float g_v   [ (size_t)ROWS * Dc ];
__device__ float g_attn[ (size_t)ROWS * Dc ];
__device__ float g_x2  [ (size_t)ROWS * Dc ];
__device__ float g_ffn [ (size_t)ROWS * 4 * Dc ];

// ---------------- LayerNorm: one block per row of 1024 ----------------
__global__ void __launch_bounds__(256) ln_kernel(const float* __restrict__ x,
                                                 const float* __restrict__ g,
                                                 const float* __restrict__ b,
                                                 float* __restrict__ o)
{
    __shared__ float sred[16];
    int row = blockIdx.x;
    int tid = threadIdx.x;
    const float* xr = x + (size_t)row * Dc;
    float4 v = *(const float4*)&xr[tid * 4];
    float s  = v.x + v.y + v.z + v.w;
    float s2 = v.x*v.x + v.y*v.y + v.z*v.z + v.w*v.w;
    #pragma unroll
    for (int off = 16; off; off >>= 1) {
        s  += __shfl_xor_sync(0xffffffffu, s,  off);
        s2 += __shfl_xor_sync(0xffffffffu, s2, off);
    }
    if ((tid & 31) == 0) { sred[tid >> 5] = s; sred[8 + (tid >> 5)] = s2; }
    __syncthreads();
    float S = 0.f, S2 = 0.f;
    #pragma unroll
    for (int i = 0; i < 8; i++) { S += sred[i]; S2 += sred[8 + i]; }
    float mean = S * (1.0f / Dc);
    float var  = S2 * (1.0f / Dc) - mean * mean;
    float rstd = rsqrtf(var + 1e-5f);
    float4 gv = *(const float4*)&g[tid * 4];
    float4 bv = *(const float4*)&b[tid * 4];
    float4 ov;
    ov.x = (v.x - mean) * rstd * gv.x + bv.x;
    ov.y = (v.y - mean) * rstd * gv.y + bv.y;
    ov.z = (v.z - mean) * rstd * gv.z + bv.z;
    ov.w = (v.w - mean) * rstd * gv.w + bv.w;
    *(float4*)&o[(size_t)row * Dc + tid * 4] = ov;
}

// ---------------- GEMM: C[M,N] = A[M,K] @ B[K,N] + bias (+ GELU) (+ residual) ----
// BM=BN=64, BK=16, 256 threads, 4x4 per thread.
__device__ __forceinline__ float gelu_f(float v)
{
    return 0.5f * v * (1.0f + erff(v * 0.70710678118654752f));
}

template<bool GELU>
__global__ void __launch_bounds__(256) gemm_kernel(
    const float* __restrict__ A, const float* __restrict__ B,
    const float* __restrict__ bias, const float* __restrict__ res,
    float* __restrict__ C, int M, int N, int K)
{
    __shared__ float sA[64][20];   // padded, 16B-aligned rows
    __shared__ float sB[16][64];

    int tid = threadIdx.x;
    int tx = tid & 15, ty = tid >> 4;
    int bm = blockIdx.y * 64, bn = blockIdx.x * 64;

    float acc[4][4] = {};

    int arow = tid >> 2;          // 0..63
    int acol = (tid & 3) * 4;     // 0,4,8,12
    int brow = tid >> 4;          // 0..15
    int bcol = (tid & 15) * 4;    // 0..60

    for (int k0 = 0; k0 < K; k0 += 16) {
        float4 a4 = *(const float4*)&A[(size_t)(bm + arow) * K + k0 + acol];
        *(float4*)&sA[arow][acol] = a4;
        float4 b4 = *(const float4*)&B[(size_t)(k0 + brow) * N + bn + bcol];
        *(float4*)&sB[brow][bcol] = b4;
        __syncthreads();
        #pragma unroll
        for (int kk = 0; kk < 16; kk++) {
            float a0 = sA[ty*4+0][kk];
            float a1 = sA[ty*4+1][kk];
            float a2 = sA[ty*4+2][kk];
            float a3 = sA[ty*4+3][kk];
            float4 bv = *(float4*)&sB[kk][tx*4];
            acc[0][0] += a0*bv.x; acc[0][1] += a0*bv.y; acc[0][2] += a0*bv.z; acc[0][3] += a0*bv.w;
            acc[1][0] += a1*bv.x; acc[1][1] += a1*bv.y; acc[1][2] += a1*bv.z; acc[1][3] += a1*bv.w;
            acc[2][0] += a2*bv.x; acc[2][1] += a2*bv.y; acc[2][2] += a2*bv.z; acc[2][3] += a2*bv.w;
            acc[3][0] += a3*bv.x; acc[3][1] += a3*bv.y; acc[3][2] += a3*bv.z; acc[3][3] += a3*bv.w;
        }
        __syncthreads();
    }

    int colbase = bn + tx * 4;
    float4 bb = *(const float4*)&bias[colbase];
    #pragma unroll
    for (int i = 0; i < 4; i++) {
        int row = bm + ty * 4 + i;
        float4 r;
        r.x = acc[i][0] + bb.x;
        r.y = acc[i][1] + bb.y;
        r.z = acc[i][2] + bb.z;
        r.w = acc[i][3] + bb.w;
        if (GELU) {
            r.x = gelu_f(r.x); r.y = gelu_f(r.y);
            r.z = gelu_f(r.z); r.w = gelu_f(r.w);
        }
        if (res) {
            float4 rv = *(const float4*)&res[(size_t)row * N + colbase];
            r.x += rv.x; r.y += rv.y; r.z += rv.z; r.w += rv.w;
        }
        *(float4*)&C[(size_t)row * N + colbase] = r;
    }
}

// ---------------- RoPE + [B,T,H,DH] -> [B,H,T,DH] transpose -------------------
__global__ void __launch_bounds__(256) rope_kernel(
    const float* __restrict__ in, const float* __restrict__ cosb,
    const float* __restrict__ sinb, float* __restrict__ out, int applyRope)
{
    int idx = blockIdx.x * blockDim.x + threadIdx.x;   // 0 .. B*T*H*NB-1
    int i = idx & 31;
    int h = (idx >> 5) & 15;
    int t = (idx >> 9) & 2047;
    int b = idx >> 20;
    const float2 xv = *(const float2*)(in + ((((size_t)b*Tc + t)*Hc + h) * DHc) + 2*i);
    float o1, o2;
    if (applyRope) {
        size_t ci = (((size_t)b*Hc + h)*Tc + t) * NBc + i;
        float c = cosb[ci], s = sinb[ci];
        o1 = xv.x * c - xv.y * s;
        o2 = xv.x * s + xv.y * c;
    } else {
        o1 = xv.x; o2 = xv.y;
    }
    float2 ov = make_float2(o1, o2);
    *(float2*)(out + ((((size_t)b*Hc + h)*Tc + t) * DHc) + 2*i) = ov;
}

// ---------------- Flash attention (causal), Q/K/V in [B,H,T,DH] ---------------
// Block: 256 threads, 64 queries x 32-key tiles, DH=64.
// Output written directly in [B,T,H,DH] layout.
__global__ void __launch_bounds__(256) attn_kernel(
    const float* __restrict__ Q, const float* __restrict__ K,
    const float* __restrict__ V, float* __restrict__ O)
{
    __shared__ float sQ[64][64];
    __shared__ float sK[32][65];
    __shared__ float sV[32][64];
    __shared__ float sP[64][32];

    int bh = blockIdx.y;
    int qb = blockIdx.x;
    int b = bh / Hc, h = bh % Hc;
    const float* Qb = Q + (size_t)bh * Tc * DHc + (size_t)qb * 64 * DHc;
    const float* Kb = K + (size_t)bh * Tc * DHc;
    const float* Vb = V + (size_t)bh * Tc * DHc;

    int tid = threadIdx.x;
    int tx = tid & 15, ty = tid >> 4;

    // load Q tile (contiguous 4096 floats), pre-scaled by 1/sqrt(DH)
    for (int e = tid * 4; e < 64 * 64; e += 1024) {
        float4 qv = *(const float4*)&Qb[e];
        qv.x *= 0.125f; qv.y *= 0.125f; qv.z *= 0.125f; qv.w *= 0.125f;
        *(float4*)&((float*)sQ)[e] = qv;
    }

    float m_i[4], l_i[4], acc[4][4];
    #pragma unroll
    for (int i = 0; i < 4; i++) {
        m_i[i] = -1e30f; l_i[i] = 0.f;
        #pragma unroll
        for (int j = 0; j < 4; j++) acc[i][j] = 0.f;
    }

    int nkt = 2 * qb + 2;   // causal: key tiles 0 .. (qb*64+63)/32
    for (int kt = 0; kt < nkt; kt++) {
        __syncthreads();    // protect sK/sV (prev reads) before reload
        const float* Kt = Kb + (size_t)kt * 32 * DHc;
        const float* Vt = Vb + (size_t)kt * 32 * DHc;
        for (int e = tid; e < 2048; e += 256)
            sK[e >> 6][e & 63] = Kt[e];
        for (int e = tid * 4; e < 2048; e += 1024)
            *(float4*)&((float*)sV)[e] = *(const float4*)&Vt[e];
        __syncthreads();

        // S = Q K^T (64 x 32), each thread: rows 4ty.., cols 2tx..
        float s[4][2] = {};
        #pragma unroll
        for (int kk = 0; kk < 64; kk++) {
            float a0 = sQ[ty*4+0][kk];
            float a1 = sQ[ty*4+1][kk];
            float a2 = sQ[ty*4+2][kk];
            float a3 = sQ[ty*4+3][kk];
            float b0 = sK[tx*2+0][kk];
            float b1 = sK[tx*2+1][kk];
            s[0][0] += a0*b0; s[0][1] += a0*b1;
            s[1][0] += a1*b0; s[1][1] += a1*b1;
            s[2][0] += a2*b0; s[2][1] += a2*b1;
            s[3][0] += a3*b0; s[3][1] += a3*b1;
        }

        // causal mask + online softmax
        #pragma unroll
        for (int i = 0; i < 4; i++) {
            int qi = qb * 64 + ty * 4 + i;
            int ki0 = kt * 32 + tx * 2;
            if (ki0 + 0 > qi) s[i][0] = -1e30f;
            if (ki0 + 1 > qi) s[i][1] = -1e30f;
            float mloc = fmaxf(s[i][0], s[i][1]);
            #pragma unroll
            for (int off = 8; off >= 1; off >>= 1)
                mloc = fmaxf(mloc, __shfl_xor_sync(0xffffffffu, mloc, off));
            float mnew  = fmaxf(m_i[i], mloc);
            float alpha = __expf(m_i[i] - mnew);
            float p0 = __expf(s[i][0] - mnew);
            float p1 = __expf(s[i][1] - mnew);
            float rs = p0 + p1;
            #pragma unroll
            for (int off = 8; off >= 1; off >>= 1)
                rs += __shfl_xor_sync(0xffffffffu, rs, off);
            l_i[i] = l_i[i] * alpha + rs;
            m_i[i] = mnew;
            #pragma unroll
            for (int j = 0; j < 4; j++) acc[i][j] *= alpha;
            sP[ty*4+i][tx*2+0] = p0;
            sP[ty*4+i][tx*2+1] = p1;
        }
        __syncthreads();

        // O += P V  (64x64 += 64x32 @ 32x64)
        #pragma unroll
        for (int n = 0; n < 32; n++) {
            float a0 = sP[ty*4+0][n];
            float a1 = sP[ty*4+1][n];
            float a2 = sP[ty*4+2][n];
            float a3 = sP[ty*4+3][n];
            float4 bv = *(float4*)&sV[n][tx*4];
            acc[0][0] += a0*bv.x; acc[0][1] += a0*bv.y; acc[0][2] += a0*bv.z; acc[0][3] += a0*bv.w;
            acc[1][0] += a1*bv.x; acc[1][1] += a1*bv.y; acc[1][2] += a1*bv.z; acc[1][3] += a1*bv.w;
            acc[2][0] += a2*bv.x; acc[2][1] += a2*bv.y; acc[2][2] += a2*bv.z; acc[2][3] += a2*bv.w;
            acc[3][0] += a3*bv.x; acc[3][1] += a3*bv.y; acc[3][2] += a3*bv.z; acc[3][3] += a3*bv.w;
        }
    }

    // epilogue: divide by l, write to [B,T,H,DH]
    #pragma unroll
    for (int i = 0; i < 4; i++) {
        float inv = 1.0f / l_i[i];
        int t = qb * 64 + ty * 4 + i;
        float* dst = O + ((((size_t)b * Tc + t) * Hc + h) * DHc) + tx * 4;
        float4 ov;
        ov.x = acc[i][0] * inv;
        ov.y = acc[i][1] * inv;
        ov.z = acc[i][2] * inv;
        ov.w = acc[i][3] * inv;
        *(float4*)dst = ov;
    }
}

// ---------------- launch ----------------
extern "C" void kernel_launch(void* const* d_in, const int* in_sizes, int n_in,
                              void* d_out, int out_size)
{
    const float* x    = (const float*)d_in[0];
    const float* cosb = (const float*)d_in[1];
    const float* sinb = (const float*)d_in[2];
    // d_in[3] = causal_mask (bool) — causality computed inline
    const float* Wq  = (const float*)d_in[4];
    const float* bq  = (const float*)d_in[5];
    const float* Wk  = (const float*)d_in[6];
    const float* bk  = (const float*)d_in[7];
    const float* Wv  = (const float*)d_in[8];
    const float* bv  = (const float*)d_in[9];
    const float* Wo  = (const float*)d_in[10];
    const float* bo  = (const float*)d_in[11];
    const float* g1  = (const float*)d_in[12];
    const float* b1n = (const float*)d_in[13];
    const float* g2  = (const float*)d_in[14];
    const float* b2n = (const float*)d_in[15];
    const float* W1  = (const float*)d_in[16];
    const float* bf1 = (const float*)d_in[17];
    const float* W2  = (const float*)d_in[18];
    const float* bf2 = (const float*)d_in[19];
    float* out = (float*)d_out;

    float *h, *tmp, *q, *k, *v, *attn, *x2, *ffn;
    cudaGetSymbolAddress((void**)&h,    g_h);
    cudaGetSymbolAddress((void**)&tmp,  g_tmp);
    cudaGetSymbolAddress((void**)&q,    g_q);
    cudaGetSymbolAddress((void**)&k,    g_k);
    cudaGetSymbolAddress((void**)&v,    g_v);
    cudaGetSymbolAddress((void**)&attn, g_attn);
    cudaGetSymbolAddress((void**)&x2,   g_x2);
    cudaGetSymbolAddress((void**)&ffn,  g_ffn);

    dim3 blk(256);
    dim3 gProj(Dc / 64, ROWS / 64);        // N=1024
    dim3 gFfn1(4 * Dc / 64, ROWS / 64);    // N=4096
    int ropeBlocks = (Bc * Tc * Hc * NBc) / 256;   // 8192

    // 1. h = LN(x)
    ln_kernel<<<ROWS, blk>>>(x, g1, b1n, h);
    // 2. Q/K/V projections + RoPE/transpose
    gemm_kernel<false><<<gProj, blk>>>(h, Wq, bq, nullptr, tmp, ROWS, Dc, Dc);
    rope_kernel<<<ropeBlocks, blk>>>(tmp, cosb, sinb, q, 1);
    gemm_kernel<false><<<gProj, blk>>>(h, Wk, bk, nullptr, tmp, ROWS, Dc, Dc);
    rope_kernel<<<ropeBlocks, blk>>>(tmp, cosb, sinb, k, 1);
    gemm_kernel<false><<<gProj, blk>>>(h, Wv, bv, nullptr, tmp, ROWS, Dc, Dc);
    rope_kernel<<<ropeBlocks, blk>>>(tmp, cosb, sinb, v, 0);
    // 3. causal flash attention
    dim3 gAttn(Tc / 64, Bc * Hc);
    attn_kernel<<<gAttn, blk>>>(q, k, v, attn);
    // 4. x2 = x + attn @ Wo + bo
    gemm_kernel<false><<<gProj, blk>>>(attn, Wo, bo, x, x2, ROWS, Dc, Dc);
    // 5. h = LN(x2)
    ln_kernel<<<ROWS, blk>>>(x2, g2, b2n, h);
    // 6. ffn = gelu(h @ W1 + bf1)
    gemm_kernel<true><<<gFfn1, blk>>>(h, W1, bf1, nullptr, ffn, ROWS, 4 * Dc, Dc);
    // 7. out = x2 + ffn @ W2 + bf2
    gemm_kernel<false><<<gProj, blk>>>(ffn, W2, bf2, x2, out, ROWS, Dc, 4 * Dc);
}

// round 2
// speedup vs baseline: 2.0979x; 2.0979x over previous
#include <cuda_runtime.h>
#include <math.h>
#include <stdint.h>

// Problem constants
#define Bc 2
#define Tc 2048
#define Dc 1024
#define Hc 16
#define DHc 64
#define NBc 32
#define ROWS (Bc*Tc)          // 4096

// ---------------- scratch (static device memory; no allocations) ----------------
__device__ float g_h   [ (size_t)ROWS * Dc ];
__device__ float g_tmp [ (size_t)ROWS * Dc ];
__device__ float g_q   [ (size_t)ROWS * Dc ];
__device__ float g_k   [ (size_t)ROWS * Dc ];
__device__ float g_v   [ (size_t)ROWS * Dc ];
__device__ float g_attn[ (size_t)ROWS * Dc ];
__device__ float g_x2  [ (size_t)ROWS * Dc ];
__device__ float g_ffn [ (size_t)ROWS * 4 * Dc ];

// ---------------- LayerNorm: one block per row of 1024 ----------------
__global__ void __launch_bounds__(256) ln_kernel(const float* __restrict__ x,
                                                 const float* __restrict__ g,
                                                 const float* __restrict__ b,
                                                 float* __restrict__ o)
{
    __shared__ float sred[16];
    int row = blockIdx.x;
    int tid = threadIdx.x;
    const float* xr = x + (size_t)row * Dc;
    float4 v = *(const float4*)&xr[tid * 4];
    float s  = v.x + v.y + v.z + v.w;
    float s2 = v.x*v.x + v.y*v.y + v.z*v.z + v.w*v.w;
    #pragma unroll
    for (int off = 16; off; off >>= 1) {
        s  += __shfl_xor_sync(0xffffffffu, s,  off);
        s2 += __shfl_xor_sync(0xffffffffu, s2, off);
    }
    if ((tid & 31) == 0) { sred[tid >> 5] = s; sred[8 + (tid >> 5)] = s2; }
    __syncthreads();
    float S = 0.f, S2 = 0.f;
    #pragma unroll
    for (int i = 0; i < 8; i++) { S += sred[i]; S2 += sred[8 + i]; }
    float mean = S * (1.0f / Dc);
    float var  = S2 * (1.0f / Dc) - mean * mean;
    float rstd = rsqrtf(var + 1e-5f);
    float4 gv = *(const float4*)&g[tid * 4];
    float4 bv = *(const float4*)&b[tid * 4];
    float4 ov;
    ov.x = (v.x - mean) * rstd * gv.x + bv.x;
    ov.y = (v.y - mean) * rstd * gv.y + bv.y;
    ov.z = (v.z - mean) * rstd * gv.z + bv.z;
    ov.w = (v.w - mean) * rstd * gv.w + bv.w;
    *(float4*)&o[(size_t)row * Dc + tid * 4] = ov;
}

// ---------------- TF32 tensor-core GEMM --------------------------------------
// C[M,N] = A[M,K] @ B[K,N] + bias (+GELU) (+res). 128x128x16 tiles, 8 warps,
// warp tile 64x32 via 4x4 m16n8k8 tf32 mma fragments. Double-buffered SMEM.

__device__ __forceinline__ float to_tf32(float x)
{
    uint32_t u;
    asm("cvt.rna.tf32.f32 %0, %1;" : "=r"(u) : "f"(x));
    return __uint_as_float(u);
}

__device__ __forceinline__ void mma_tf32(float c[4],
    uint32_t a0, uint32_t a1, uint32_t a2, uint32_t a3,
    uint32_t b0, uint32_t b1)
{
    asm volatile(
        "mma.sync.aligned.m16n8k8.row.col.f32.tf32.tf32.f32 "
        "{%0,%1,%2,%3}, {%4,%5,%6,%7}, {%8,%9}, {%0,%1,%2,%3};"
        : "+f"(c[0]), "+f"(c[1]), "+f"(c[2]), "+f"(c[3])
        : "r"(a0), "r"(a1), "r"(a2), "r"(a3), "r"(b0), "r"(b1));
}

__device__ __forceinline__ float gelu_f(float v)
{
    return 0.5f * v * (1.0f + erff(v * 0.70710678118654752f));
}

template<bool GELU>
__global__ void __launch_bounds__(256) gemm_tf32_kernel(
    const float* __restrict__ A, const float* __restrict__ B,
    const float* __restrict__ bias, const float* __restrict__ res,
    float* __restrict__ C, int M, int N, int K)
{
    __shared__ float sA[2][128][20];   // stride 20: conflict-free frag reads
    __shared__ float sB[2][16][136];   // stride 136: conflict-free frag reads

    int tid  = threadIdx.x;
    int lane = tid & 31;
    int warp = tid >> 5;
    int wm = (warp & 1) * 64;
    int wn = (warp >> 1) * 32;
    int bm = blockIdx.y * 128, bn = blockIdx.x * 128;

    // global load mapping
    int ar = tid >> 2;            // 0..63 (two rows: ar, ar+64)
    int ac = (tid & 3) * 4;       // 0,4,8,12
    int br = tid >> 5;            // 0..7  (two rows: br, br+8)
    int bc = (tid & 31) * 4;      // 0..124

    const float* Aptr = A + (size_t)(bm + ar) * K + ac;
    const float* Bptr = B + (size_t)br * N + bn + bc;

    float acc[4][4][4];
    #pragma unroll
    for (int i = 0; i < 4; i++)
        #pragma unroll
        for (int j = 0; j < 4; j++)
            #pragma unroll
            for (int r = 0; r < 4; r++) acc[i][j][r] = 0.f;

    int ntiles = K / 16;

    // prologue: tile 0 -> buffer 0
    {
        float4 a0 = *(const float4*)(Aptr);
        float4 a1 = *(const float4*)(Aptr + (size_t)64 * K);
        float4 b0 = *(const float4*)(Bptr);
        float4 b1 = *(const float4*)(Bptr + (size_t)8 * N);
        float4 ca0 = make_float4(to_tf32(a0.x), to_tf32(a0.y), to_tf32(a0.z), to_tf32(a0.w));
        float4 ca1 = make_float4(to_tf32(a1.x), to_tf32(a1.y), to_tf32(a1.z), to_tf32(a1.w));
        float4 cb0 = make_float4(to_tf32(b0.x), to_tf32(b0.y), to_tf32(b0.z), to_tf32(b0.w));
        float4 cb1 = make_float4(to_tf32(b1.x), to_tf32(b1.y), to_tf32(b1.z), to_tf32(b1.w));
        *(float4*)&sA[0][ar][ac]      = ca0;
        *(float4*)&sA[0][ar + 64][ac] = ca1;
        *(float4*)&sB[0][br][bc]      = cb0;
        *(float4*)&sB[0][br + 8][bc]  = cb1;
    }
    __syncthreads();

    for (int t = 0; t < ntiles; t++) {
        int buf = t & 1;
        float4 pa0, pa1, pb0, pb1;
        bool pref = (t + 1 < ntiles);
        if (pref) {
            const float* Ap = Aptr + (t + 1) * 16;
            pa0 = *(const float4*)(Ap);
            pa1 = *(const float4*)(Ap + (size_t)64 * K);
            const float* Bp = Bptr + (size_t)(t + 1) * 16 * N;
            pb0 = *(const float4*)(Bp);
            pb1 = *(const float4*)(Bp + (size_t)8 * N);
        }

        #pragma unroll
        for (int ks = 0; ks < 16; ks += 8) {
            uint32_t af[4][4], bf[4][2];
            #pragma unroll
            for (int mi = 0; mi < 4; mi++) {
                int r0 = wm + mi * 16 + (lane >> 2);
                int c0 = ks + (lane & 3);
                af[mi][0] = __float_as_uint(sA[buf][r0][c0]);
                af[mi][1] = __float_as_uint(sA[buf][r0 + 8][c0]);
                af[mi][2] = __float_as_uint(sA[buf][r0][c0 + 4]);
                af[mi][3] = __float_as_uint(sA[buf][r0 + 8][c0 + 4]);
            }
            #pragma unroll
            for (int ni = 0; ni < 4; ni++) {
                int col = wn + ni * 8 + (lane >> 2);
                bf[ni][0] = __float_as_uint(sB[buf][ks + (lane & 3)][col]);
                bf[ni][1] = __float_as_uint(sB[buf][ks + (lane & 3) + 4][col]);
            }
            #pragma unroll
            for (int mi = 0; mi < 4; mi++)
                #pragma unroll
                for (int ni = 0; ni < 4; ni++)
                    mma_tf32(acc[mi][ni], af[mi][0], af[mi][1], af[mi][2], af[mi][3],
                             bf[ni][0], bf[ni][1]);
        }

        if (pref) {
            int nb = buf ^ 1;
            float4 ca0 = make_float4(to_tf32(pa0.x), to_tf32(pa0.y), to_tf32(pa0.z), to_tf32(pa0.w));
            float4 ca1 = make_float4(to_tf32(pa1.x), to_tf32(pa1.y), to_tf32(pa1.z), to_tf32(pa1.w));
            float4 cb0 = make_float4(to_tf32(pb0.x), to_tf32(pb0.y), to_tf32(pb0.z), to_tf32(pb0.w));
            float4 cb1 = make_float4(to_tf32(pb1.x), to_tf32(pb1.y), to_tf32(pb1.z), to_tf32(pb1.w));
            *(float4*)&sA[nb][ar][ac]      = ca0;
            *(float4*)&sA[nb][ar + 64][ac] = ca1;
            *(float4*)&sB[nb][br][bc]      = cb0;
            *(float4*)&sB[nb][br + 8][bc]  = cb1;
        }
        __syncthreads();
    }

    // epilogue
    #pragma unroll
    for (int mi = 0; mi < 4; mi++) {
        int row = bm + wm + mi * 16 + (lane >> 2);
        #pragma unroll
        for (int ni = 0; ni < 4; ni++) {
            int col = bn + wn + ni * 8 + 2 * (lane & 3);
            float2 bb = *(const float2*)&bias[col];
            float2 r01 = make_float2(acc[mi][ni][0] + bb.x, acc[mi][ni][1] + bb.y);
            float2 r23 = make_float2(acc[mi][ni][2] + bb.x, acc[mi][ni][3] + bb.y);
            if (GELU) {
                r01.x = gelu_f(r01.x); r01.y = gelu_f(r01.y);
                r23.x = gelu_f(r23.x); r23.y = gelu_f(r23.y);
            }
            if (res) {
                float2 v0 = *(const float2*)&res[(size_t)row * N + col];
                float2 v1 = *(const float2*)&res[(size_t)(row + 8) * N + col];
                r01.x += v0.x; r01.y += v0.y;
                r23.x += v1.x; r23.y += v1.y;
            }
            *(float2*)&C[(size_t)row * N + col] = r01;
            *(float2*)&C[(size_t)(row + 8) * N + col] = r23;
        }
    }
}

// ---------------- RoPE + [B,T,H,DH] -> [B,H,T,DH] transpose -------------------
__global__ void __launch_bounds__(256) rope_kernel(
    const float* __restrict__ in, const float* __restrict__ cosb,
    const float* __restrict__ sinb, float* __restrict__ out, int applyRope)
{
    int idx = blockIdx.x * blockDim.x + threadIdx.x;   // 0 .. B*T*H*NB-1
    int i = idx & 31;
    int h = (idx >> 5) & 15;
    int t = (idx >> 9) & 2047;
    int b = idx >> 20;
    const float2 xv = *(const float2*)(in + ((((size_t)b*Tc + t)*Hc + h) * DHc) + 2*i);
    float o1, o2;
    if (applyRope) {
        size_t ci = (((size_t)b*Hc + h)*Tc + t) * NBc + i;
        float c = cosb[ci], s = sinb[ci];
        o1 = xv.x * c - xv.y * s;
        o2 = xv.x * s + xv.y * c;
    } else {
        o1 = xv.x; o2 = xv.y;
    }
    float2 ov = make_float2(o1, o2);
    *(float2*)(out + ((((size_t)b*Hc + h)*Tc + t) * DHc) + 2*i) = ov;
}

// ---------------- Flash attention (causal), Q/K/V in [B,H,T,DH] ---------------
__global__ void __launch_bounds__(256) attn_kernel(
    const float* __restrict__ Q, const float* __restrict__ K,
    const float* __restrict__ V, float* __restrict__ O)
{
    __shared__ float sQ[64][64];
    __shared__ float sK[32][65];
    __shared__ float sV[32][64];
    __shared__ float sP[64][32];

    int bh = blockIdx.y;
    int qb = blockIdx.x;
    int b = bh / Hc, h = bh % Hc;
    const float* Qb = Q + (size_t)bh * Tc * DHc + (size_t)qb * 64 * DHc;
    const float* Kb = K + (size_t)bh * Tc * DHc;
    const float* Vb = V + (size_t)bh * Tc * DHc;

    int tid = threadIdx.x;
    int tx = tid & 15, ty = tid >> 4;

    for (int e = tid * 4; e < 64 * 64; e += 1024) {
        float4 qv = *(const float4*)&Qb[e];
        qv.x *= 0.125f; qv.y *= 0.125f; qv.z *= 0.125f; qv.w *= 0.125f;
        *(float4*)&((float*)sQ)[e] = qv;
    }

    float m_i[4], l_i[4], acc[4][4];
    #pragma unroll
    for (int i = 0; i < 4; i++) {
        m_i[i] = -1e30f; l_i[i] = 0.f;
        #pragma unroll
        for (int j = 0; j < 4; j++) acc[i][j] = 0.f;
    }

    int nkt = 2 * qb + 2;
    for (int kt = 0; kt < nkt; kt++) {
        __syncthreads();
        const float* Kt = Kb + (size_t)kt * 32 * DHc;
        const float* Vt = Vb + (size_t)kt * 32 * DHc;
        for (int e = tid; e < 2048; e += 256)
            sK[e >> 6][e & 63] = Kt[e];
        for (int e = tid * 4; e < 2048; e += 1024)
            *(float4*)&((float*)sV)[e] = *(const float4*)&Vt[e];
        __syncthreads();

        float s[4][2] = {};
        #pragma unroll
        for (int kk = 0; kk < 64; kk++) {
            float a0 = sQ[ty*4+0][kk];
            float a1 = sQ[ty*4+1][kk];
            float a2 = sQ[ty*4+2][kk];
            float a3 = sQ[ty*4+3][kk];
            float b0 = sK[tx*2+0][kk];
            float b1 = sK[tx*2+1][kk];
            s[0][0] += a0*b0; s[0][1] += a0*b1;
            s[1][0] += a1*b0; s[1][1] += a1*b1;
            s[2][0] += a2*b0; s[2][1] += a2*b1;
            s[3][0] += a3*b0; s[3][1] += a3*b1;
        }

        #pragma unroll
        for (int i = 0; i < 4; i++) {
            int qi = qb * 64 + ty * 4 + i;
            int ki0 = kt * 32 + tx * 2;
            if (ki0 + 0 > qi) s[i][0] = -1e30f;
            if (ki0 + 1 > qi) s[i][1] = -1e30f;
            float mloc = fmaxf(s[i][0], s[i][1]);
            #pragma unroll
            for (int off = 8; off >= 1; off >>= 1)
                mloc = fmaxf(mloc, __shfl_xor_sync(0xffffffffu, mloc, off));
            float mnew  = fmaxf(m_i[i], mloc);
            float alpha = __expf(m_i[i] - mnew);
            float p0 = __expf(s[i][0] - mnew);
            float p1 = __expf(s[i][1] - mnew);
            float rs = p0 + p1;
            #pragma unroll
            for (int off = 8; off >= 1; off >>= 1)
                rs += __shfl_xor_sync(0xffffffffu, rs, off);
            l_i[i] = l_i[i] * alpha + rs;
            m_i[i] = mnew;
            #pragma unroll
            for (int j = 0; j < 4; j++) acc[i][j] *= alpha;
            sP[ty*4+i][tx*2+0] = p0;
            sP[ty*4+i][tx*2+1] = p1;
        }
        __syncthreads();

        #pragma unroll
        for (int n = 0; n < 32; n++) {
            float a0 = sP[ty*4+0][n];
            float a1 = sP[ty*4+1][n];
            float a2 = sP[ty*4+2][n];
            float a3 = sP[ty*4+3][n];
            float4 bv = *(float4*)&sV[n][tx*4];
            acc[0][0] += a0*bv.x; acc[0][1] += a0*bv.y; acc[0][2] += a0*bv.z; acc[0][3] += a0*bv.w;
            acc[1][0] += a1*bv.x; acc[1][1] += a1*bv.y; acc[1][2] += a1*bv.z; acc[1][3] += a1*bv.w;
            acc[2][0] += a2*bv.x; acc[2][1] += a2*bv.y; acc[2][2] += a2*bv.z; acc[2][3] += a2*bv.w;
            acc[3][0] += a3*bv.x; acc[3][1] += a3*bv.y; acc[3][2] += a3*bv.z; acc[3][3] += a3*bv.w;
        }
    }

    #pragma unroll
    for (int i = 0; i < 4; i++) {
        float inv = 1.0f / l_i[i];
        int t = qb * 64 + ty * 4 + i;
        float* dst = O + ((((size_t)b * Tc + t) * Hc + h) * DHc) + tx * 4;
        float4 ov;
        ov.x = acc[i][0] * inv;
        ov.y = acc[i][1] * inv;
        ov.z = acc[i][2] * inv;
        ov.w = acc[i][3] * inv;
        *(float4*)dst = ov;
    }
}

// ---------------- launch ----------------
extern "C" void kernel_launch(void* const* d_in, const int* in_sizes, int n_in,
                              void* d_out, int out_size)
{
    const float* x    = (const float*)d_in[0];
    const float* cosb = (const float*)d_in[1];
    const float* sinb = (const float*)d_in[2];
    // d_in[3] = causal_mask (bool) — causality computed inline
    const float* Wq  = (const float*)d_in[4];
    const float* bq  = (const float*)d_in[5];
    const float* Wk  = (const float*)d_in[6];
    const float* bk  = (const float*)d_in[7];
    const float* Wv  = (const float*)d_in[8];
    const float* bv  = (const float*)d_in[9];
    const float* Wo  = (const float*)d_in[10];
    const float* bo  = (const float*)d_in[11];
    const float* g1  = (const float*)d_in[12];
    const float* b1n = (const float*)d_in[13];
    const float* g2  = (const float*)d_in[14];
    const float* b2n = (const float*)d_in[15];
    const float* W1  = (const float*)d_in[16];
    const float* bf1 = (const float*)d_in[17];
    const float* W2  = (const float*)d_in[18];
    const float* bf2 = (const float*)d_in[19];
    float* out = (float*)d_out;

    float *h, *tmp, *q, *k, *v, *attn, *x2, *ffn;
    cudaGetSymbolAddress((void**)&h,    g_h);
    cudaGetSymbolAddress((void**)&tmp,  g_tmp);
    cudaGetSymbolAddress((void**)&q,    g_q);
    cudaGetSymbolAddress((void**)&k,    g_k);
    cudaGetSymbolAddress((void**)&v,    g_v);
    cudaGetSymbolAddress((void**)&attn, g_attn);
    cudaGetSymbolAddress((void**)&x2,   g_x2);
    cudaGetSymbolAddress((void**)&ffn,  g_ffn);

    dim3 blk(256);
    dim3 gProj(Dc / 128, ROWS / 128);        // (8, 32)
    dim3 gFfn1(4 * Dc / 128, ROWS / 128);    // (32, 32)
    int ropeBlocks = (Bc * Tc * Hc * NBc) / 256;   // 8192

    // 1. h = LN(x)
    ln_kernel<<<ROWS, blk>>>(x, g1, b1n, h);
    // 2. Q/K/V projections + RoPE/transpose
    gemm_tf32_kernel<false><<<gProj, blk>>>(h, Wq, bq, nullptr, tmp, ROWS, Dc, Dc);
    rope_kernel<<<ropeBlocks, blk>>>(tmp, cosb, sinb, q, 1);
    gemm_tf32_kernel<false><<<gProj, blk>>>(h, Wk, bk, nullptr, tmp, ROWS, Dc, Dc);
    rope_kernel<<<ropeBlocks, blk>>>(tmp, cosb, sinb, k, 1);
    gemm_tf32_kernel<false><<<gProj, blk>>>(h, Wv, bv, nullptr, tmp, ROWS, Dc, Dc);
    rope_kernel<<<ropeBlocks, blk>>>(tmp, cosb, sinb, v, 0);
    // 3. causal flash attention
    dim3 gAttn(Tc / 64, Bc * Hc);
    attn_kernel<<<gAttn, blk>>>(q, k, v, attn);
    // 4. x2 = x + attn @ Wo + bo
    gemm_tf32_kernel<false><<<gProj, blk>>>(attn, Wo, bo, x, x2, ROWS, Dc, Dc);
    // 5. h = LN(x2)
    ln_kernel<<<ROWS, blk>>>(x2, g2, b2n, h);
    // 6. ffn = gelu(h @ W1 + bf1)
    gemm_tf32_kernel<true><<<gFfn1, blk>>>(h, W1, bf1, nullptr, ffn, ROWS, 4 * Dc, Dc);
    // 7. out = x2 + ffn @ W2 + bf2
    gemm_tf32_kernel<false><<<gProj, blk>>>(ffn, W2, bf2, x2, out, ROWS, Dc, 4 * Dc);
}

// round 3
// speedup vs baseline: 2.8521x; 1.3595x over previous
#include <cuda_runtime.h>
#include <math.h>
#include <stdint.h>

// Problem constants
#define Bc 2
#define Tc 2048
#define Dc 1024
#define Hc 16
#define DHc 64
#define NBc 32
#define ROWS (Bc*Tc)          // 4096

// ---------------- scratch ----------------
__device__ float g_h   [ (size_t)ROWS * Dc ];
__device__ float g_tmp [ (size_t)ROWS * Dc ];
__device__ float g_q   [ (size_t)ROWS * Dc ];
__device__ float g_k   [ (size_t)ROWS * Dc ];
__device__ float g_v   [ (size_t)ROWS * Dc ];
__device__ float g_attn[ (size_t)ROWS * Dc ];
__device__ float g_x2  [ (size_t)ROWS * Dc ];
__device__ float g_ffn [ (size_t)ROWS * 4 * Dc ];

// ---------------- helpers ----------------
__device__ __forceinline__ float to_tf32(float x)
{
    uint32_t u;
    asm("cvt.rna.tf32.f32 %0, %1;" : "=r"(u) : "f"(x));
    return __uint_as_float(u);
}

__device__ __forceinline__ void mma8(float c[4],
    float a0, float a1, float a2, float a3, float b0, float b1)
{
    asm volatile(
        "mma.sync.aligned.m16n8k8.row.col.f32.tf32.tf32.f32 "
        "{%0,%1,%2,%3}, {%4,%5,%6,%7}, {%8,%9}, {%0,%1,%2,%3};"
        : "+f"(c[0]), "+f"(c[1]), "+f"(c[2]), "+f"(c[3])
        : "r"(__float_as_uint(a0)), "r"(__float_as_uint(a1)),
          "r"(__float_as_uint(a2)), "r"(__float_as_uint(a3)),
          "r"(__float_as_uint(b0)), "r"(__float_as_uint(b1)));
}

// A-operand layout (row-major m x k): [r][chunk16 | 4*((k&3)^(r&3)) | (k>>2)&3]
__device__ __forceinline__ int a_idx(int r, int k, int stride)
{
    return r * stride + ((k >> 4) << 4) + 4 * (((k & 3) ^ (r & 3))) + ((k >> 2) & 3);
}
// B-operand layout (k x n accessed col-major): rows are n
__device__ __forceinline__ int b_idx(int n, int k, int stride)
{
    return n * stride + ((k >> 4) << 4)
         + 4 * (((k & 3) ^ (n & 3) ^ ((n >> 2) & 3))) + ((k >> 2) & 3);
}

__device__ __forceinline__ float gelu_f(float v)
{
    return 0.5f * v * (1.0f + erff(v * 0.70710678118654752f));
}

// ---------------- LayerNorm ----------------
__global__ void __launch_bounds__(256) ln_kernel(const float* __restrict__ x,
                                                 const float* __restrict__ g,
                                                 const float* __restrict__ b,
                                                 float* __restrict__ o)
{
    __shared__ float sred[16];
    int row = blockIdx.x;
    int tid = threadIdx.x;
    const float* xr = x + (size_t)row * Dc;
    float4 v = *(const float4*)&xr[tid * 4];
    float s  = v.x + v.y + v.z + v.w;
    float s2 = v.x*v.x + v.y*v.y + v.z*v.z + v.w*v.w;
    #pragma unroll
    for (int off = 16; off; off >>= 1) {
        s  += __shfl_xor_sync(0xffffffffu, s,  off);
        s2 += __shfl_xor_sync(0xffffffffu, s2, off);
    }
    if ((tid & 31) == 0) { sred[tid >> 5] = s; sred[8 + (tid >> 5)] = s2; }
    __syncthreads();
    float S = 0.f, S2 = 0.f;
    #pragma unroll
    for (int i = 0; i < 8; i++) { S += sred[i]; S2 += sred[8 + i]; }
    float mean = S * (1.0f / Dc);
    float var  = S2 * (1.0f / Dc) - mean * mean;
    float rstd = rsqrtf(var + 1e-5f);
    float4 gv = *(const float4*)&g[tid * 4];
    float4 bv = *(const float4*)&b[tid * 4];
    float4 ov;
    ov.x = (v.x - mean) * rstd * gv.x + bv.x;
    ov.y = (v.y - mean) * rstd * gv.y + bv.y;
    ov.z = (v.z - mean) * rstd * gv.z + bv.z;
    ov.w = (v.w - mean) * rstd * gv.w + bv.w;
    *(float4*)&o[(size_t)row * Dc + tid * 4] = ov;
}

// ---------------- TF32 GEMM, fragment-permuted A smem -------------------------
template<bool GELU>
__global__ void __launch_bounds__(256) gemm_tc(
    const float* __restrict__ A, const float* __restrict__ B,
    const float* __restrict__ bias, const float* __restrict__ res,
    float* __restrict__ C, int M, int N, int K)
{
    __shared__ float sA[2][128 * 16];
    __shared__ float sB[2][16][136];

    int tid  = threadIdx.x;
    int lane = tid & 31;
    int warp = tid >> 5;
    int q4 = lane & 3, rr = lane >> 2;
    int wm = (warp & 1) * 64;
    int wn = (warp >> 1) * 32;
    int bm = blockIdx.y * 128, bn = blockIdx.x * 128;

    int ar = tid >> 2;            // A rows ar, ar+64
    int ac = (tid & 3) * 4;
    int br = tid >> 5;            // B rows br, br+8
    int bc = (tid & 31) * 4;

    const float* Aptr = A + (size_t)(bm + ar) * K + ac;
    const float* Bptr = B + (size_t)br * N + bn + bc;

    // A store positions: k = ac+j -> k&3=j, inner=(tid&3); rows ar & ar+64 share pos
    int axor = ar & 3;
    int ap0 = 4 * ((0 ^ axor)) + (tid & 3);
    int ap1 = 4 * ((1 ^ axor)) + (tid & 3);
    int ap2 = 4 * ((2 ^ axor)) + (tid & 3);
    int ap3 = 4 * ((3 ^ axor)) + (tid & 3);

    float acc[4][4][4];
    #pragma unroll
    for (int i = 0; i < 4; i++)
        #pragma unroll
        for (int j = 0; j < 4; j++)
            #pragma unroll
            for (int r = 0; r < 4; r++) acc[i][j][r] = 0.f;

    int ntiles = K / 16;

    // prologue: tile 0
    {
        float4 a0 = *(const float4*)(Aptr);
        float4 a1 = *(const float4*)(Aptr + (size_t)64 * K);
        float4 b0 = *(const float4*)(Bptr);
        float4 b1 = *(const float4*)(Bptr + (size_t)8 * N);
        sA[0][ar * 16 + ap0] = to_tf32(a0.x);
        sA[0][ar * 16 + ap1] = to_tf32(a0.y);
        sA[0][ar * 16 + ap2] = to_tf32(a0.z);
        sA[0][ar * 16 + ap3] = to_tf32(a0.w);
        sA[0][(ar + 64) * 16 + ap0] = to_tf32(a1.x);
        sA[0][(ar + 64) * 16 + ap1] = to_tf32(a1.y);
        sA[0][(ar + 64) * 16 + ap2] = to_tf32(a1.z);
        sA[0][(ar + 64) * 16 + ap3] = to_tf32(a1.w);
        *(float4*)&sB[0][br][bc] = make_float4(to_tf32(b0.x), to_tf32(b0.y), to_tf32(b0.z), to_tf32(b0.w));
        *(float4*)&sB[0][br + 8][bc] = make_float4(to_tf32(b1.x), to_tf32(b1.y), to_tf32(b1.z), to_tf32(b1.w));
    }
    __syncthreads();

    int agrp = 4 * (q4 ^ (rr & 3));   // A-frag read group offset

    for (int t = 0; t < ntiles; t++) {
        int buf = t & 1;
        float4 pa0, pa1, pb0, pb1;
        bool pref = (t + 1 < ntiles);
        if (pref) {
            const float* Ap = Aptr + (t + 1) * 16;
            pa0 = *(const float4*)(Ap);
            pa1 = *(const float4*)(Ap + (size_t)64 * K);
            const float* Bp = Bptr + (size_t)(t + 1) * 16 * N;
            pb0 = *(const float4*)(Bp);
            pb1 = *(const float4*)(Bp + (size_t)8 * N);
        }

        // hoist B fragments: bf[ks][ni][j]
        float bf[2][4][2];
        #pragma unroll
        for (int ks = 0; ks < 2; ks++)
            #pragma unroll
            for (int ni = 0; ni < 4; ni++) {
                int col = wn + ni * 8 + rr;
                bf[ks][ni][0] = sB[buf][ks * 8 + q4][col];
                bf[ks][ni][1] = sB[buf][ks * 8 + q4 + 4][col];
            }

        #pragma unroll
        for (int mi = 0; mi < 4; mi++) {
            int r0 = wm + mi * 16 + rr;
            float4 lo = *(float4*)&sA[buf][r0 * 16 + agrp];
            float4 hi = *(float4*)&sA[buf][(r0 + 8) * 16 + agrp];
            #pragma unroll
            for (int ni = 0; ni < 4; ni++) {
                mma8(acc[mi][ni], lo.x, hi.x, lo.y, hi.y, bf[0][ni][0], bf[0][ni][1]);
                mma8(acc[mi][ni], lo.z, hi.z, lo.w, hi.w, bf[1][ni][0], bf[1][ni][1]);
            }
        }

        if (pref) {
            int nb = buf ^ 1;
            sA[nb][ar * 16 + ap0] = to_tf32(pa0.x);
            sA[nb][ar * 16 + ap1] = to_tf32(pa0.y);
            sA[nb][ar * 16 + ap2] = to_tf32(pa0.z);
            sA[nb][ar * 16 + ap3] = to_tf32(pa0.w);
            sA[nb][(ar + 64) * 16 + ap0] = to_tf32(pa1.x);
            sA[nb][(ar + 64) * 16 + ap1] = to_tf32(pa1.y);
            sA[nb][(ar + 64) * 16 + ap2] = to_tf32(pa1.z);
            sA[nb][(ar + 64) * 16 + ap3] = to_tf32(pa1.w);
            *(float4*)&sB[nb][br][bc] = make_float4(to_tf32(pb0.x), to_tf32(pb0.y), to_tf32(pb0.z), to_tf32(pb0.w));
            *(float4*)&sB[nb][br + 8][bc] = make_float4(to_tf32(pb1.x), to_tf32(pb1.y), to_tf32(pb1.z), to_tf32(pb1.w));
        }
        __syncthreads();
    }

    // epilogue
    #pragma unroll
    for (int mi = 0; mi < 4; mi++) {
        int row = bm + wm + mi * 16 + rr;
        #pragma unroll
        for (int ni = 0; ni < 4; ni++) {
            int col = bn + wn + ni * 8 + 2 * q4;
            float2 bb = *(const float2*)&bias[col];
            float2 r01 = make_float2(acc[mi][ni][0] + bb.x, acc[mi][ni][1] + bb.y);
            float2 r23 = make_float2(acc[mi][ni][2] + bb.x, acc[mi][ni][3] + bb.y);
            if (GELU) {
                r01.x = gelu_f(r01.x); r01.y = gelu_f(r01.y);
                r23.x = gelu_f(r23.x); r23.y = gelu_f(r23.y);
            }
            if (res) {
                float2 v0 = *(const float2*)&res[(size_t)row * N + col];
                float2 v1 = *(const float2*)&res[(size_t)(row + 8) * N + col];
                r01.x += v0.x; r01.y += v0.y;
                r23.x += v1.x; r23.y += v1.y;
            }
            *(float2*)&C[(size_t)row * N + col] = r01;
            *(float2*)&C[(size_t)(row + 8) * N + col] = r23;
        }
    }
}

// ---------------- RoPE + transpose -------------------
__global__ void __launch_bounds__(256) rope_kernel(
    const float* __restrict__ in, const float* __restrict__ cosb,
    const float* __restrict__ sinb, float* __restrict__ out, int applyRope)
{
    int idx = blockIdx.x * blockDim.x + threadIdx.x;
    int i = idx & 31;
    int h = (idx >> 5) & 15;
    int t = (idx >> 9) & 2047;
    int b = idx >> 20;
    const float2 xv = *(const float2*)(in + ((((size_t)b*Tc + t)*Hc + h) * DHc) + 2*i);
    float o1, o2;
    if (applyRope) {
        size_t ci = (((size_t)b*Hc + h)*Tc + t) * NBc + i;
        float c = cosb[ci], s = sinb[ci];
        o1 = xv.x * c - xv.y * s;
        o2 = xv.x * s + xv.y * c;
    } else {
        o1 = xv.x; o2 = xv.y;
    }
    *(float2*)(out + ((((size_t)b*Hc + h)*Tc + t) * DHc) + 2*i) = make_float2(o1, o2);
}

// ---------------- Tensor-core flash attention ---------------------------------
// Q-tile 128, K-tile 64, 8 warps; warp w owns rows [16w, 16w+16).
#define ASTR 80

__global__ void __launch_bounds__(256) attn_tc(
    const float* __restrict__ Q, const float* __restrict__ K,
    const float* __restrict__ V, float* __restrict__ O)
{
    extern __shared__ float sm[];
    float* sQ  = sm;                    // [128][ASTR] A-layout
    float* sP  = sm + 128 * ASTR;       // [128][ASTR] A-layout
    float* sKt = sm + 256 * ASTR;       // [64][ASTR]  B-layout (n=key, k=dh)
    float* sVt = sKt + 64 * ASTR;       // [64][ASTR]  B-layout (n=dh, k=key)

    int tid = threadIdx.x, lane = tid & 31, warp = tid >> 5;
    int q4 = lane & 3, rr = lane >> 2;
    int bh = blockIdx.y;
    int b = bh >> 4, h = bh & 15;
    int qb = gridDim.x - 1 - blockIdx.x;   // big tiles first

    const float* Qb = Q + ((size_t)bh * Tc + (size_t)qb * 128) * DHc;
    const float* Kb = K + (size_t)bh * Tc * DHc;
    const float* Vb = V + (size_t)bh * Tc * DHc;

    // load Q tile (128x64), scale by 1/sqrt(DH), A-layout
    #pragma unroll
    for (int jj = 0; jj < 8; jj++) {
        int f4 = tid + 256 * jj;
        int r = f4 >> 4, kb = (f4 & 15) * 4;
        float4 qv = *(const float4*)&Qb[r * 64 + kb];
        sQ[a_idx(r, kb + 0, ASTR)] = to_tf32(qv.x * 0.125f);
        sQ[a_idx(r, kb + 1, ASTR)] = to_tf32(qv.y * 0.125f);
        sQ[a_idx(r, kb + 2, ASTR)] = to_tf32(qv.z * 0.125f);
        sQ[a_idx(r, kb + 3, ASTR)] = to_tf32(qv.w * 0.125f);
    }

    float m0 = -1e30f, m1 = -1e30f, l0 = 0.f, l1 = 0.f;
    float o[8][4];
    #pragma unroll
    for (int ni = 0; ni < 8; ni++)
        #pragma unroll
        for (int j = 0; j < 4; j++) o[ni][j] = 0.f;

    int r0 = 16 * warp + rr;           // local row (and r0+8)
    int rowg = qb * 128 + r0;          // global row
    int agrp = 4 * (q4 ^ (r0 & 3));    // A-frag group offset (same for r0+8)

    int nkt = 2 * qb + 2;
    for (int kt = 0; kt < nkt; kt++) {
        __syncthreads();
        const float* Kt = Kb + (size_t)kt * 64 * DHc;
        const float* Vt = Vb + (size_t)kt * 64 * DHc;
        #pragma unroll
        for (int jj = 0; jj < 4; jj++) {
            int f4 = tid + 256 * jj;
            int n = f4 >> 4, kb = (f4 & 15) * 4;
            float4 kv = *(const float4*)&Kt[n * 64 + kb];
            sKt[b_idx(n, kb + 0, ASTR)] = to_tf32(kv.x);
            sKt[b_idx(n, kb + 1, ASTR)] = to_tf32(kv.y);
            sKt[b_idx(n, kb + 2, ASTR)] = to_tf32(kv.z);
            sKt[b_idx(n, kb + 3, ASTR)] = to_tf32(kv.w);
            float4 vv = *(const float4*)&Vt[n * 64 + kb];   // n=key, kb=dh
            sVt[b_idx(kb + 0, n, ASTR)] = to_tf32(vv.x);
            sVt[b_idx(kb + 1, n, ASTR)] = to_tf32(vv.y);
            sVt[b_idx(kb + 2, n, ASTR)] = to_tf32(vv.z);
            sVt[b_idx(kb + 3, n, ASTR)] = to_tf32(vv.w);
        }
        __syncthreads();

        // S = Q K^T : warp computes 16x64
        float s[8][4];
        #pragma unroll
        for (int ni = 0; ni < 8; ni++)
            #pragma unroll
            for (int j = 0; j < 4; j++) s[ni][j] = 0.f;

        #pragma unroll
        for (int ch = 0; ch < 4; ch++) {
            float4 lo = *(float4*)&sQ[r0 * ASTR + ch * 16 + agrp];
            float4 hi = *(float4*)&sQ[(r0 + 8) * ASTR + ch * 16 + agrp];
            #pragma unroll
            for (int ni = 0; ni < 8; ni++) {
                int n0 = ni * 8 + rr;
                float4 fb = *(float4*)&sKt[n0 * ASTR + ch * 16
                                + 4 * (q4 ^ (n0 & 3) ^ ((n0 >> 2) & 3))];
                mma8(s[ni], lo.x, hi.x, lo.y, hi.y, fb.x, fb.y);
                mma8(s[ni], lo.z, hi.z, lo.w, hi.w, fb.z, fb.w);
            }
        }

        // causal mask (only diagonal tiles)
        if (kt >= 2 * qb) {
            #pragma unroll
            for (int ni = 0; ni < 8; ni++) {
                int colg = kt * 64 + ni * 8 + 2 * q4;
                if (colg     > rowg)     s[ni][0] = -1e30f;
                if (colg + 1 > rowg)     s[ni][1] = -1e30f;
                if (colg     > rowg + 8) s[ni][2] = -1e30f;
                if (colg + 1 > rowg + 8) s[ni][3] = -1e30f;
            }
        }

        // online softmax (warp-local; rows r0, r0+8)
        float mx0 = -1e30f, mx1 = -1e30f;
        #pragma unroll
        for (int ni = 0; ni < 8; ni++) {
            mx0 = fmaxf(mx0, fmaxf(s[ni][0], s[ni][1]));
            mx1 = fmaxf(mx1, fmaxf(s[ni][2], s[ni][3]));
        }
        mx0 = fmaxf(mx0, __shfl_xor_sync(0xffffffffu, mx0, 1));
        mx0 = fmaxf(mx0, __shfl_xor_sync(0xffffffffu, mx0, 2));
        mx1 = fmaxf(mx1, __shfl_xor_sync(0xffffffffu, mx1, 1));
        mx1 = fmaxf(mx1, __shfl_xor_sync(0xffffffffu, mx1, 2));
        float mn0 = fmaxf(m0, mx0), mn1 = fmaxf(m1, mx1);
        float al0 = __expf(m0 - mn0), al1 = __expf(m1 - mn1);
        m0 = mn0; m1 = mn1;

        float sum0 = 0.f, sum1 = 0.f;
        #pragma unroll
        for (int ni = 0; ni < 8; ni++) {
            int kl = ni * 8 + 2 * q4;   // local key index within tile
            float p0 = __expf(s[ni][0] - m0);
            float p1 = __expf(s[ni][1] - m0);
            float p2 = __expf(s[ni][2] - m1);
            float p3 = __expf(s[ni][3] - m1);
            sum0 += p0 + p1; sum1 += p2 + p3;
            sP[a_idx(r0,     kl,     ASTR)] = p0;
            sP[a_idx(r0,     kl + 1, ASTR)] = p1;
            sP[a_idx(r0 + 8, kl,     ASTR)] = p2;
            sP[a_idx(r0 + 8, kl + 1, ASTR)] = p3;
        }
        sum0 += __shfl_xor_sync(0xffffffffu, sum0, 1);
        sum0 += __shfl_xor_sync(0xffffffffu, sum0, 2);
        sum1 += __shfl_xor_sync(0xffffffffu, sum1, 1);
        sum1 += __shfl_xor_sync(0xffffffffu, sum1, 2);
        l0 = l0 * al0 + sum0;
        l1 = l1 * al1 + sum1;

        #pragma unroll
        for (int ni = 0; ni < 8; ni++) {
            o[ni][0] *= al0; o[ni][1] *= al0;
            o[ni][2] *= al1; o[ni][3] *= al1;
        }
        __syncwarp();

        // O += P V : warp 16x64
        #pragma unroll
        for (int ch = 0; ch < 4; ch++) {
            float4 lo = *(float4*)&sP[r0 * ASTR + ch * 16 + agrp];
            float4 hi = *(float4*)&sP[(r0 + 8) * ASTR + ch * 16 + agrp];
            #pragma unroll
            for (int ni = 0; ni < 8; ni++) {
                int n0 = ni * 8 + rr;
                float4 fb = *(float4*)&sVt[n0 * ASTR + ch * 16
                                + 4 * (q4 ^ (n0 & 3) ^ ((n0 >> 2) & 3))];
                mma8(o[ni], lo.x, hi.x, lo.y, hi.y, fb.x, fb.y);
                mma8(o[ni], lo.z, hi.z, lo.w, hi.w, fb.z, fb.w);
            }
        }
    }

    // epilogue: /l, write [B,T,H,DH]
    float inv0 = 1.f / l0, inv1 = 1.f / l1;
    int t0 = qb * 128 + r0;
    #pragma unroll
    for (int ni = 0; ni < 8; ni++) {
        int dh = ni * 8 + 2 * q4;
        *(float2*)&O[((((size_t)b * Tc + t0) * Hc + h) * DHc) + dh] =
            make_float2(o[ni][0] * inv0, o[ni][1] * inv0);
        *(float2*)&O[((((size_t)b * Tc + t0 + 8) * Hc + h) * DHc) + dh] =
            make_float2(o[ni][2] * inv1, o[ni][3] * inv1);
    }
}

// ---------------- launch ----------------
extern "C" void kernel_launch(void* const* d_in, const int* in_sizes, int n_in,
                              void* d_out, int out_size)
{
    const float* x    = (const float*)d_in[0];
    const float* cosb = (const float*)d_in[1];
    const float* sinb = (const float*)d_in[2];
    const float* Wq  = (const float*)d_in[4];
    const float* bq  = (const float*)d_in[5];
    const float* Wk  = (const float*)d_in[6];
    const float* bk  = (const float*)d_in[7];
    const float* Wv  = (const float*)d_in[8];
    const float* bv  = (const float*)d_in[9];
    const float* Wo  = (const float*)d_in[10];
    const float* bo  = (const float*)d_in[11];
    const float* g1  = (const float*)d_in[12];
    const float* b1n = (const float*)d_in[13];
    const float* g2  = (const float*)d_in[14];
    const float* b2n = (const float*)d_in[15];
    const float* W1  = (const float*)d_in[16];
    const float* bf1 = (const float*)d_in[17];
    const float* W2  = (const float*)d_in[18];
    const float* bf2 = (const float*)d_in[19];
    float* out = (float*)d_out;

    float *h, *tmp, *q, *k, *v, *attn, *x2, *ffn;
    cudaGetSymbolAddress((void**)&h,    g_h);
    cudaGetSymbolAddress((void**)&tmp,  g_tmp);
    cudaGetSymbolAddress((void**)&q,    g_q);
    cudaGetSymbolAddress((void**)&k,    g_k);
    cudaGetSymbolAddress((void**)&v,    g_v);
    cudaGetSymbolAddress((void**)&attn, g_attn);
    cudaGetSymbolAddress((void**)&x2,   g_x2);
    cudaGetSymbolAddress((void**)&ffn,  g_ffn);

    int attnSmem = (2 * 128 + 2 * 64) * ASTR * (int)sizeof(float);   // 122880
    cudaFuncSetAttribute(attn_tc, cudaFuncAttributeMaxDynamicSharedMemorySize, attnSmem);

    dim3 blk(256);
    dim3 gProj(Dc / 128, ROWS / 128);
    dim3 gFfn1(4 * Dc / 128, ROWS / 128);
    int ropeBlocks = (Bc * Tc * Hc * NBc) / 256;

    ln_kernel<<<ROWS, blk>>>(x, g1, b1n, h);
    gemm_tc<false><<<gProj, blk>>>(h, Wq, bq, nullptr, tmp, ROWS, Dc, Dc);
    rope_kernel<<<ropeBlocks, blk>>>(tmp, cosb, sinb, q, 1);
    gemm_tc<false><<<gProj, blk>>>(h, Wk, bk, nullptr, tmp, ROWS, Dc, Dc);
    rope_kernel<<<ropeBlocks, blk>>>(tmp, cosb, sinb, k, 1);
    gemm_tc<false><<<gProj, blk>>>(h, Wv, bv, nullptr, tmp, ROWS, Dc, Dc);
    rope_kernel<<<ropeBlocks, blk>>>(tmp, cosb, sinb, v, 0);

    dim3 gAttn(Tc / 128, Bc * Hc);
    attn_tc<<<gAttn, blk, attnSmem>>>(q, k, v, attn);

    gemm_tc<false><<<gProj, blk>>>(attn, Wo, bo, x, x2, ROWS, Dc, Dc);
    ln_kernel<<<ROWS, blk>>>(x2, g2, b2n, h);
    gemm_tc<true><<<gFfn1, blk>>>(h, W1, bf1, nullptr, ffn, ROWS, 4 * Dc, Dc);
    gemm_tc<false><<<gProj, blk>>>(ffn, W2, bf2, x2, out, ROWS, Dc, 4 * Dc);
}